// round 1
// baseline (speedup 1.0000x reference)
#include <cuda_runtime.h>
#include <cstdint>
#include <type_traits>

// Problem constants
#define B_  32
#define N_  1024
#define K_  12
#define H_  64
#define BN_ (B_ * N_)        // 32768 nodes
#define ME_ (BN_ * K_)       // 393216 edges

// ---------------- scratch (static device allocations; no cudaMalloc) -------
__device__ float g_dist[(size_t)B_ * N_ * N_];   // 128 MB
__device__ int   g_idx[ME_];
__device__ float g_d2[BN_];
__device__ float g_h1[(size_t)ME_ * H_];          // 100 MB
__device__ float g_f0[(size_t)BN_ * H_];
__device__ float g_f1[(size_t)BN_ * H_];
__device__ float g_sum[H_];
__device__ float g_sqs[H_];
__device__ float g_scale[H_];
__device__ float g_shift[H_];
__device__ float g_pool[B_ * H_];

// ---------------- squared norms --------------------------------------------
template<int CIN>
__global__ void d2_kernel(const float* __restrict__ F) {
    int w    = (blockIdx.x * blockDim.x + threadIdx.x) >> 5;  // node id
    int lane = threadIdx.x & 31;
    const float* row = F + (size_t)w * CIN;
    float s = 0.f;
    for (int c = lane; c < CIN; c += 32) { float v = row[c]; s = fmaf(v, v, s); }
    #pragma unroll
    for (int o = 16; o; o >>= 1) s += __shfl_down_sync(0xffffffffu, s, o);
    if (lane == 0) g_d2[w] = s;
}

// ---------------- pairwise distances: dist = d2_i + d2_j - 2 x_i.x_j -------
// Tile: 64 rows(i) x 128 cols(j), 256 threads, 4x8 microtile.
template<int CIN>
__global__ __launch_bounds__(256) void dist_kernel(const float* __restrict__ F) {
    constexpr int CB = (CIN < 32) ? CIN : 32;   // k-chunk (CIN in {3,64})
    __shared__ float Xi[64][33];
    __shared__ float Xj[128][33];
    __shared__ float d2i[64], d2j[128];

    int tx = threadIdx.x, ty = threadIdx.y;
    int t  = ty * 16 + tx;
    int b  = blockIdx.z;
    int i0 = blockIdx.y * 64, j0 = blockIdx.x * 128;
    const float* Fb = F + (size_t)b * N_ * CIN;

    if (t < 64)  d2i[t] = g_d2[b * N_ + i0 + t];
    if (t < 128) d2j[t] = g_d2[b * N_ + j0 + t];

    float acc[4][8];
    #pragma unroll
    for (int m = 0; m < 4; ++m)
        #pragma unroll
        for (int n = 0; n < 8; ++n) acc[m][n] = 0.f;

    for (int c0 = 0; c0 < CIN; c0 += CB) {
        __syncthreads();
        for (int i = t; i < 64 * CB; i += 256) {
            int r = i / CB, k = i - r * CB;
            Xi[r][k] = Fb[(size_t)(i0 + r) * CIN + c0 + k];
        }
        for (int i = t; i < 128 * CB; i += 256) {
            int r = i / CB, k = i - r * CB;
            Xj[r][k] = Fb[(size_t)(j0 + r) * CIN + c0 + k];
        }
        __syncthreads();
        #pragma unroll
        for (int k = 0; k < CB; ++k) {
            float a[4], bb[8];
            #pragma unroll
            for (int m = 0; m < 4; ++m) a[m] = Xi[ty * 4 + m][k];
            #pragma unroll
            for (int n = 0; n < 8; ++n) bb[n] = Xj[tx + 16 * n][k];
            #pragma unroll
            for (int m = 0; m < 4; ++m)
                #pragma unroll
                for (int n = 0; n < 8; ++n) acc[m][n] = fmaf(a[m], bb[n], acc[m][n]);
        }
    }

    float* D = g_dist + ((size_t)b * N_ + i0) * N_ + j0;
    #pragma unroll
    for (int m = 0; m < 4; ++m) {
        float di = d2i[ty * 4 + m];
        #pragma unroll
        for (int n = 0; n < 8; ++n) {
            D[(size_t)(ty * 4 + m) * N_ + tx + 16 * n] =
                di + d2j[tx + 16 * n] - 2.0f * acc[m][n];
        }
    }
}

// ---------------- top-K (K=12 smallest, tie -> lowest index) ---------------
__global__ void topk_kernel() {
    int row  = (blockIdx.x * blockDim.x + threadIdx.x) >> 5;
    int lane = threadIdx.x & 31;
    const float* dr = g_dist + (size_t)row * N_;

    float bd[12]; int bj[12];
    #pragma unroll
    for (int i = 0; i < 12; ++i) { bd[i] = 3.4e38f; bj[i] = 1 << 30; }

    for (int j = lane; j < N_; j += 32) {
        float d = dr[j];
        if (d < bd[11] || (d == bd[11] && j < bj[11])) {
            bd[11] = d; bj[11] = j;
            #pragma unroll
            for (int s = 11; s > 0; --s) {
                bool sw = (bd[s] < bd[s-1]) || (bd[s] == bd[s-1] && bj[s] < bj[s-1]);
                float td = sw ? bd[s-1] : bd[s];
                float th = sw ? bd[s]   : bd[s-1];
                int   tj = sw ? bj[s-1] : bj[s];
                int   ti = sw ? bj[s]   : bj[s-1];
                bd[s] = td; bd[s-1] = th; bj[s] = tj; bj[s-1] = ti;
            }
        }
    }

    int keep = 0;
    #pragma unroll 1
    for (int r = 0; r < 12; ++r) {
        float wd = bd[0]; int wj = bj[0];
        #pragma unroll
        for (int o = 16; o; o >>= 1) {
            float od = __shfl_down_sync(0xffffffffu, wd, o);
            int   oj = __shfl_down_sync(0xffffffffu, wj, o);
            if (od < wd || (od == wd && oj < wj)) { wd = od; wj = oj; }
        }
        wj = __shfl_sync(0xffffffffu, wj, 0);
        if (wj == bj[0]) {   // this lane's head won (j unique across lanes)
            #pragma unroll
            for (int s = 0; s < 11; ++s) { bd[s] = bd[s+1]; bj[s] = bj[s+1]; }
            bd[11] = 3.4e38f; bj[11] = 1 << 30;
        }
        if (lane == r) keep = wj;
    }
    if (lane < 12) g_idx[row * 12 + lane] = keep;
}

// ---------------- stats helpers --------------------------------------------
__global__ void zero_stats() {
    int t = threadIdx.x;
    if (t < H_) { g_sum[t] = 0.f; g_sqs[t] = 0.f; }
}

__global__ void finalize_stats(const float* __restrict__ g, const float* __restrict__ be) {
    int h = threadIdx.x;
    const float invM = 1.f / (float)ME_;
    float m = g_sum[h] * invM;
    float v = g_sqs[h] * invM - m * m;
    float sc = g[h] * rsqrtf(v + 1e-5f);
    g_scale[h] = sc;
    g_shift[h] = fmaf(-m, sc, be[h]);
}

// ---------------- edge features + MLP1 (h1 = [xi, xj-xi] @ W1 + b1) --------
// Tile: 128 edges x 64 outputs, 256 threads, 8x4 microtile.
template<int CIN>
__global__ __launch_bounds__(256) void edge_h1_kernel(const float* __restrict__ F,
                                                      const float* __restrict__ W1,
                                                      const float* __restrict__ b1) {
    constexpr int EDIM = 2 * CIN;
    __shared__ float Es[32][129];
    __shared__ float Ws[32][65];
    __shared__ int   xin[128], xjn[128];
    __shared__ float ssum[64], ssqs[64];

    int t  = threadIdx.x;
    int tx = t & 15, ty = t >> 4;
    int e0 = blockIdx.x * 128;

    if (t < 128) {
        int gg   = e0 + t;
        int node = gg / K_;
        xin[t] = node;
        xjn[t] = ((node >> 10) << 10) + g_idx[gg];
    }
    if (t < 64) { ssum[t] = 0.f; ssqs[t] = 0.f; }

    float acc[8][4];
    #pragma unroll
    for (int m = 0; m < 8; ++m)
        #pragma unroll
        for (int n = 0; n < 4; ++n) acc[m][n] = 0.f;

    for (int c0 = 0; c0 < EDIM; c0 += 32) {
        __syncthreads();
        for (int i = t; i < 128 * 32; i += 256) {
            int e = i >> 5, k = i & 31;
            int c = c0 + k;
            float v = 0.f;
            if (c < EDIM) {
                if (c < CIN) v = F[(size_t)xin[e] * CIN + c];
                else {
                    int cc = c - CIN;
                    v = F[(size_t)xjn[e] * CIN + cc] - F[(size_t)xin[e] * CIN + cc];
                }
            }
            Es[k][e] = v;
        }
        for (int i = t; i < 32 * 64; i += 256) {
            int k = i >> 6, h = i & 63;
            int c = c0 + k;
            Ws[k][h] = (c < EDIM) ? W1[c * 64 + h] : 0.f;
        }
        __syncthreads();
        #pragma unroll
        for (int k = 0; k < 32; ++k) {
            float a[8], bv[4];
            #pragma unroll
            for (int m = 0; m < 8; ++m) a[m] = Es[k][ty * 8 + m];
            #pragma unroll
            for (int n = 0; n < 4; ++n) bv[n] = Ws[k][tx + 16 * n];
            #pragma unroll
            for (int m = 0; m < 8; ++m)
                #pragma unroll
                for (int n = 0; n < 4; ++n) acc[m][n] = fmaf(a[m], bv[n], acc[m][n]);
        }
    }

    #pragma unroll
    for (int n = 0; n < 4; ++n) {
        int h = tx + 16 * n;
        float bvv = b1[h];
        float s = 0.f, q = 0.f;
        #pragma unroll
        for (int m = 0; m < 8; ++m) {
            float v = acc[m][n] + bvv;
            g_h1[(size_t)(e0 + ty * 8 + m) * 64 + h] = v;
            s += v; q = fmaf(v, v, q);
        }
        atomicAdd(&ssum[h], s);
        atomicAdd(&ssqs[h], q);
    }
    __syncthreads();
    if (t < 64) { atomicAdd(&g_sum[t], ssum[t]); atomicAdd(&g_sqs[t], ssqs[t]); }
}

// ---------------- BN + ReLU + mean over K + W2 GEMM ------------------------
// mean_k(relu(bn(h1)))@W2 + b2  (mean commutes with the linear layer)
__global__ __launch_bounds__(256) void bn_mlp2_kernel(float* __restrict__ Fout,
                                                      const float* __restrict__ W2,
                                                      const float* __restrict__ b2) {
    __shared__ float As[64][65];
    __shared__ float Ws[64][65];
    int t  = threadIdx.x;
    int tx = t & 15, ty = t >> 4;
    int n0 = blockIdx.x * 64;

    for (int i = t; i < 64 * 64; i += 256) Ws[i >> 6][i & 63] = W2[i];

    for (int i = t; i < 64 * 64; i += 256) {
        int node = i >> 6, h = i & 63;
        float scv = g_scale[h], shv = g_shift[h];
        const float* p = g_h1 + (size_t)(n0 + node) * K_ * 64 + h;
        float s = 0.f;
        #pragma unroll
        for (int k = 0; k < K_; ++k)
            s += fmaxf(fmaf(p[k * 64], scv, shv), 0.f);
        As[h][node] = s * (1.f / 12.f);
    }
    __syncthreads();

    float acc[4][4];
    #pragma unroll
    for (int m = 0; m < 4; ++m)
        #pragma unroll
        for (int n = 0; n < 4; ++n) acc[m][n] = 0.f;

    #pragma unroll
    for (int h = 0; h < 64; ++h) {
        float a[4], bv[4];
        #pragma unroll
        for (int m = 0; m < 4; ++m) a[m] = As[h][ty * 4 + m];
        #pragma unroll
        for (int n = 0; n < 4; ++n) bv[n] = Ws[h][tx + 16 * n];
        #pragma unroll
        for (int m = 0; m < 4; ++m)
            #pragma unroll
            for (int n = 0; n < 4; ++n) acc[m][n] = fmaf(a[m], bv[n], acc[m][n]);
    }

    #pragma unroll
    for (int n = 0; n < 4; ++n) {
        int o = tx + 16 * n;
        float bo = b2[o];
        #pragma unroll
        for (int m = 0; m < 4; ++m)
            Fout[(size_t)(n0 + ty * 4 + m) * 64 + o] = acc[m][n] + bo;
    }
}

// ---------------- global mean pool over nodes ------------------------------
__global__ void pool_kernel(const float* __restrict__ F) {
    __shared__ float red[4][64];
    int t = threadIdx.x;
    int h = t & 63, s = t >> 6;
    int b = blockIdx.x;
    float acc = 0.f;
    for (int n = s; n < N_; n += 4)
        acc += F[((size_t)b * N_ + n) * H_ + h];
    red[s][h] = acc;
    __syncthreads();
    if (t < 64)
        g_pool[b * H_ + t] = (red[0][t] + red[1][t] + red[2][t] + red[3][t]) * (1.f / N_);
}

// ---------------- FC head: Linear + BN(batch) + ReLU + Linear --------------
__global__ void fc_kernel(const float* __restrict__ wf1, const float* __restrict__ bf1,
                          const float* __restrict__ gf,  const float* __restrict__ bef,
                          const float* __restrict__ wf2, const float* __restrict__ bf2,
                          float* __restrict__ out) {
    __shared__ float zs[32][33];
    __shared__ float sc[32], sh[32];
    int t = threadIdx.x;
    int b = t >> 5, j = t & 31;

    float acc = bf1[j];
    #pragma unroll
    for (int h = 0; h < 64; ++h)
        acc = fmaf(g_pool[b * 64 + h], wf1[h * 32 + j], acc);
    zs[b][j] = acc;
    __syncthreads();

    if (t < 32) {
        float s = 0.f;
        for (int q = 0; q < 32; ++q) s += zs[q][t];
        float m = s * (1.f / 32.f);
        float v = 0.f;
        for (int q = 0; q < 32; ++q) { float d = zs[q][t] - m; v = fmaf(d, d, v); }
        v *= (1.f / 32.f);
        float s2 = gf[t] * rsqrtf(v + 1e-5f);
        sc[t] = s2;
        sh[t] = fmaf(-m, s2, bef[t]);
    }
    __syncthreads();

    float r = fmaxf(fmaf(zs[b][j], sc[j], sh[j]), 0.f);
    zs[b][j] = r;   // each thread overwrites only its own element
    __syncthreads();

    if (t < 64) {
        int q = t >> 1, o = t & 1;
        float a = bf2[o];
        #pragma unroll
        for (int jj = 0; jj < 32; ++jj)
            a = fmaf(zs[q][jj], wf2[jj * 2 + o], a);
        out[q * 2 + o] = a;
    }
}

// ---------------- host ------------------------------------------------------
template<int CIN>
static void run_layer(const float* Fin, float* Fout,
                      const float* W1, const float* b1,
                      const float* g, const float* be,
                      const float* W2, const float* b2) {
    d2_kernel<CIN><<<4096, 256>>>(Fin);
    dist_kernel<CIN><<<dim3(8, 16, 32), dim3(16, 16)>>>(Fin);
    topk_kernel<<<4096, 256>>>();
    zero_stats<<<1, 64>>>();
    edge_h1_kernel<CIN><<<3072, 256>>>(Fin, W1, b1);
    finalize_stats<<<1, 64>>>(g, be);
    bn_mlp2_kernel<<<512, 256>>>(Fout, W2, b2);
}

extern "C" void kernel_launch(void* const* d_in, const int* in_sizes, int n_in,
                              void* d_out, int out_size) {
    const float* x   = (const float*)d_in[0];
    const float* w0a = (const float*)d_in[1];
    const float* b0a = (const float*)d_in[2];
    const float* g0  = (const float*)d_in[3];
    const float* be0 = (const float*)d_in[4];
    const float* w0b = (const float*)d_in[5];
    const float* b0b = (const float*)d_in[6];
    const float* wa  = (const float*)d_in[7];
    const float* ba  = (const float*)d_in[8];
    const float* ga  = (const float*)d_in[9];
    const float* bea = (const float*)d_in[10];
    const float* wb  = (const float*)d_in[11];
    const float* bb  = (const float*)d_in[12];
    const float* wf1 = (const float*)d_in[13];
    const float* bf1 = (const float*)d_in[14];
    const float* gf  = (const float*)d_in[15];
    const float* bef = (const float*)d_in[16];
    const float* wf2 = (const float*)d_in[17];
    const float* bf2 = (const float*)d_in[18];
    float* out = (float*)d_out;

    float *f0 = nullptr, *f1 = nullptr;
    cudaGetSymbolAddress((void**)&f0, g_f0);
    cudaGetSymbolAddress((void**)&f1, g_f1);

    // layer 0: CIN = 3
    run_layer<3>(x, f0, w0a, b0a, g0, be0, w0b, b0b);
    // layers 1..3: CIN = 64
    run_layer<64>(f0, f1, wa,              ba,       ga,       bea,       wb,            bb);
    run_layer<64>(f1, f0, wa + 128 * 64,   ba + 64,  ga + 64,  bea + 64,  wb + 64 * 64,  bb + 64);
    run_layer<64>(f0, f1, wa + 256 * 64,   ba + 128, ga + 128, bea + 128, wb + 128 * 64, bb + 128);

    pool_kernel<<<32, 256>>>(f1);
    fc_kernel<<<1, 1024>>>(wf1, bf1, gf, bef, wf2, bf2, out);
}

// round 3
// speedup vs baseline: 1.6252x; 1.6252x over previous
#include <cuda_runtime.h>
#include <cstdint>

#define B_  32
#define N_  1024
#define K_  12
#define H_  64
#define BN_ (B_ * N_)        // 32768 nodes
#define ME_ (BN_ * K_)       // 393216 edges

// ---------------- scratch (static; no cudaMalloc) --------------------------
__device__ float g_dist[(size_t)B_ * N_ * N_];   // 128 MB
__device__ int   g_idx[ME_];
__device__ float g_d2[BN_];
__device__ float g_R[(size_t)BN_ * H_];          // P - Q + b1
__device__ float g_Q[(size_t)BN_ * H_];
__device__ float g_f0[(size_t)BN_ * H_];
__device__ float g_f1[(size_t)BN_ * H_];
__device__ float g_sum[H_];
__device__ float g_sqs[H_];
__device__ float g_scale[H_];
__device__ float g_shift[H_];
__device__ float g_pool[B_ * H_];

__device__ __forceinline__ float f4c(const float4& v, int i) {
    return i == 0 ? v.x : i == 1 ? v.y : i == 2 ? v.z : v.w;
}

// ---------------- squared norms --------------------------------------------
template<int CIN>
__global__ void d2_kernel(const float* __restrict__ F) {
    int w    = (blockIdx.x * blockDim.x + threadIdx.x) >> 5;
    int lane = threadIdx.x & 31;
    const float* row = F + (size_t)w * CIN;
    float s = 0.f;
    for (int c = lane; c < CIN; c += 32) { float v = row[c]; s = fmaf(v, v, s); }
    #pragma unroll
    for (int o = 16; o; o >>= 1) s += __shfl_down_sync(0xffffffffu, s, o);
    if (lane == 0) g_d2[w] = s;
}

// ---------------- pairwise distances ---------------------------------------
// 128x128 tile, 8x8 microtile, k-vectorized fragments.
template<int CIN>
__global__ __launch_bounds__(256) void dist_kernel(const float* __restrict__ F) {
    constexpr int CB = (CIN < 32) ? CIN : 32;
    __shared__ __align__(16) float Xi[128][36];
    __shared__ __align__(16) float Xj[128][36];
    __shared__ float d2i[128], d2j[128];

    int tx = threadIdx.x, ty = threadIdx.y;
    int t  = ty * 16 + tx;
    int b  = blockIdx.z;
    int i0 = blockIdx.y * 128, j0 = blockIdx.x * 128;
    const float* Fb = F + (size_t)b * N_ * CIN;

    if (t < 128) { d2i[t] = g_d2[b * N_ + i0 + t]; d2j[t] = g_d2[b * N_ + j0 + t]; }

    float acc[8][8];
    #pragma unroll
    for (int m = 0; m < 8; ++m)
        #pragma unroll
        for (int n = 0; n < 8; ++n) acc[m][n] = 0.f;

    for (int c0 = 0; c0 < CIN; c0 += CB) {
        __syncthreads();
        for (int i = t; i < 128 * CB; i += 256) {
            int r = i / CB, k = i - r * CB;
            Xi[r][k] = Fb[(size_t)(i0 + r) * CIN + c0 + k];
            Xj[r][k] = Fb[(size_t)(j0 + r) * CIN + c0 + k];
        }
        __syncthreads();
        if (CIN >= 32) {
            #pragma unroll
            for (int k = 0; k < CB; k += 4) {
                float4 b4[8];
                #pragma unroll
                for (int n = 0; n < 8; ++n)
                    b4[n] = *(const float4*)&Xj[tx + 16 * n][k];
                #pragma unroll
                for (int m = 0; m < 8; ++m) {
                    float4 a4 = *(const float4*)&Xi[ty * 8 + m][k];
                    #pragma unroll
                    for (int kk = 0; kk < 4; ++kk) {
                        float av = f4c(a4, kk);
                        #pragma unroll
                        for (int n = 0; n < 8; ++n)
                            acc[m][n] = fmaf(av, f4c(b4[n], kk), acc[m][n]);
                    }
                }
            }
        } else {
            #pragma unroll
            for (int k = 0; k < CB; ++k) {
                float bv[8];
                #pragma unroll
                for (int n = 0; n < 8; ++n) bv[n] = Xj[tx + 16 * n][k];
                #pragma unroll
                for (int m = 0; m < 8; ++m) {
                    float av = Xi[ty * 8 + m][k];
                    #pragma unroll
                    for (int n = 0; n < 8; ++n)
                        acc[m][n] = fmaf(av, bv[n], acc[m][n]);
                }
            }
        }
    }

    float* D = g_dist + ((size_t)b * N_ + i0) * N_ + j0;
    #pragma unroll
    for (int m = 0; m < 8; ++m) {
        int r = ty * 8 + m;
        float di = d2i[r];
        #pragma unroll
        for (int n = 0; n < 8; ++n)
            D[(size_t)r * N_ + tx + 16 * n] = di + d2j[tx + 16 * n] - 2.0f * acc[m][n];
    }
}

// ---------------- top-K (K=12 smallest, tie -> lowest index) ---------------
__device__ __forceinline__ unsigned fkey(float d) {
    unsigned u = __float_as_uint(d);
    return (u & 0x80000000u) ? ~u : (u | 0x80000000u);
}

__global__ __launch_bounds__(256) void topk_kernel() {
    int row  = (blockIdx.x * blockDim.x + threadIdx.x) >> 5;
    int lane = threadIdx.x & 31;
    const float* dr = g_dist + (size_t)row * N_;

    unsigned long long lst[12];
    #pragma unroll
    for (int i = 0; i < 12; ++i) lst[i] = ~0ULL;

    for (int it = 0; it < 8; ++it) {
        int jb = it * 128 + lane * 4;
        float4 dv = *(const float4*)(dr + jb);
        #pragma unroll
        for (int c = 0; c < 4; ++c) {
            unsigned long long key =
                ((unsigned long long)fkey(f4c(dv, c)) << 32) | (unsigned)(jb + c);
            if (key < lst[11]) {
                lst[11] = key;
                #pragma unroll
                for (int s = 11; s > 0; --s) {
                    unsigned long long lo = lst[s] < lst[s-1] ? lst[s] : lst[s-1];
                    unsigned long long hi = lst[s] < lst[s-1] ? lst[s-1] : lst[s];
                    lst[s-1] = lo; lst[s] = hi;
                }
            }
        }
    }

    int keep = 0;
    #pragma unroll 1
    for (int r = 0; r < 12; ++r) {
        unsigned long long w = lst[0];
        #pragma unroll
        for (int o = 16; o; o >>= 1) {
            unsigned long long ow = __shfl_down_sync(0xffffffffu, w, o);
            w = ow < w ? ow : w;
        }
        w = __shfl_sync(0xffffffffu, w, 0);
        if (lst[0] == w) {
            #pragma unroll
            for (int s = 0; s < 11; ++s) lst[s] = lst[s + 1];
            lst[11] = ~0ULL;
        }
        if (lane == r) keep = (int)(w & 0xFFFFFFFFu);
    }
    if (lane < 12) g_idx[row * 12 + lane] = keep;
}

// ---------------- node-level MLP1 decomposition ----------------------------
// [P|Q] = F @ W1 (W1a = rows 0..CIN-1, W1b = rows CIN..2CIN-1)
// R = P - Q + b1 ; h1(edge i,j) = R[i] + Q[j]
__global__ __launch_bounds__(256) void pq64_kernel(const float* __restrict__ F,
                                                   const float* __restrict__ W1,
                                                   const float* __restrict__ b1) {
    __shared__ __align__(16) float Xs[128][36];
    __shared__ __align__(16) float Wt[128][36];
    int tx = threadIdx.x, ty = threadIdx.y;
    int t  = ty * 16 + tx;
    int n0 = blockIdx.x * 128;

    float acc[8][8];
    #pragma unroll
    for (int m = 0; m < 8; ++m)
        #pragma unroll
        for (int n = 0; n < 8; ++n) acc[m][n] = 0.f;

    for (int c0 = 0; c0 < 64; c0 += 32) {
        __syncthreads();
        for (int i = t; i < 128 * 32; i += 256) {
            int r = i >> 5, k = i & 31;
            Xs[r][k] = F[(size_t)(n0 + r) * 64 + c0 + k];
            Wt[r][k] = W1[(c0 + k + ((r >> 6) << 6)) * 64 + (r & 63)];
        }
        __syncthreads();
        #pragma unroll
        for (int k = 0; k < 32; k += 4) {
            float4 b4[8];
            #pragma unroll
            for (int n = 0; n < 8; ++n)
                b4[n] = *(const float4*)&Wt[tx + 16 * n][k];
            #pragma unroll
            for (int m = 0; m < 8; ++m) {
                float4 a4 = *(const float4*)&Xs[ty * 8 + m][k];
                #pragma unroll
                for (int kk = 0; kk < 4; ++kk) {
                    float av = f4c(a4, kk);
                    #pragma unroll
                    for (int n = 0; n < 8; ++n)
                        acc[m][n] = fmaf(av, f4c(b4[n], kk), acc[m][n]);
                }
            }
        }
    }

    #pragma unroll
    for (int m = 0; m < 8; ++m) {
        size_t node = n0 + ty * 8 + m;
        #pragma unroll
        for (int n = 0; n < 4; ++n) {
            int h = tx + 16 * n;
            float P = acc[m][n], Q = acc[m][n + 4];
            g_R[node * 64 + h] = P - Q + b1[h];
            g_Q[node * 64 + h] = Q;
        }
    }
}

__global__ void pq3_kernel(const float* __restrict__ x,
                           const float* __restrict__ W1,
                           const float* __restrict__ b1) {
    int gid = blockIdx.x * 256 + threadIdx.x;    // node*64 + h
    int node = gid >> 6, h = gid & 63;
    const float* xr = x + node * 3;
    float x0 = xr[0], x1 = xr[1], x2 = xr[2];
    float P = fmaf(x0, W1[h],       fmaf(x1, W1[64 + h],  x2 * W1[128 + h]));
    float Q = fmaf(x0, W1[192 + h], fmaf(x1, W1[256 + h], x2 * W1[320 + h]));
    g_R[gid] = P - Q + b1[h];
    g_Q[gid] = Q;
}

// ---------------- BN stats over all edges ----------------------------------
__global__ void zero_stats() {
    int t = threadIdx.x;
    if (t < H_) { g_sum[t] = 0.f; g_sqs[t] = 0.f; }
}

__global__ __launch_bounds__(256) void stats_kernel() {
    __shared__ float ssum[64], ssqs[64];
    int t = threadIdx.x, lane = t & 31, w = t >> 5;
    if (t < 64) { ssum[t] = 0.f; ssqs[t] = 0.f; }
    __syncthreads();

    int h = lane * 2;
    const int EPB = ME_ / 1024;    // 384 edges/block
    const int EPW = EPB / 8;       // 48 edges/warp
    int e0 = blockIdx.x * EPB + w * EPW;
    float s0 = 0.f, s1 = 0.f, q0 = 0.f, q1 = 0.f;
    #pragma unroll 4
    for (int e = e0; e < e0 + EPW; ++e) {
        int i = e / 12;
        int j = ((i >> 10) << 10) + g_idx[e];
        float2 r  = *(const float2*)&g_R[(size_t)i * 64 + h];
        float2 qv = *(const float2*)&g_Q[(size_t)j * 64 + h];
        float v0 = r.x + qv.x, v1 = r.y + qv.y;
        s0 += v0; s1 += v1;
        q0 = fmaf(v0, v0, q0); q1 = fmaf(v1, v1, q1);
    }
    atomicAdd(&ssum[h], s0);     atomicAdd(&ssum[h + 1], s1);
    atomicAdd(&ssqs[h], q0);     atomicAdd(&ssqs[h + 1], q1);
    __syncthreads();
    if (t < 64) { atomicAdd(&g_sum[t], ssum[t]); atomicAdd(&g_sqs[t], ssqs[t]); }
}

__global__ void finalize_stats(const float* __restrict__ g, const float* __restrict__ be) {
    int h = threadIdx.x;
    const float invM = 1.f / (float)ME_;
    float m = g_sum[h] * invM;
    float v = g_sqs[h] * invM - m * m;
    float sc = g[h] * rsqrtf(v + 1e-5f);
    g_scale[h] = sc;
    g_shift[h] = fmaf(-m, sc, be[h]);
}

// ---------------- BN + ReLU + mean over K + W2 GEMM ------------------------
__global__ __launch_bounds__(256) void bn_mlp2_kernel(float* __restrict__ Fout,
                                                      const float* __restrict__ W2,
                                                      const float* __restrict__ b2) {
    __shared__ float As[64][65];
    __shared__ float Ws[64][65];
    int t  = threadIdx.x;
    int n0 = blockIdx.x * 64;

    for (int i = t; i < 64 * 64; i += 256) Ws[i >> 6][i & 63] = W2[i];

    {
        int nloc = t >> 2;
        int node = n0 + nloc;
        int hq   = (t & 3) * 16;
        float R[16], sc[16], sh[16], a[16];
        #pragma unroll
        for (int p = 0; p < 4; ++p) {
            *(float4*)&R[p * 4]  = *(const float4*)&g_R[(size_t)node * 64 + hq + p * 4];
            *(float4*)&sc[p * 4] = *(const float4*)&g_scale[hq + p * 4];
            *(float4*)&sh[p * 4] = *(const float4*)&g_shift[hq + p * 4];
        }
        #pragma unroll
        for (int r = 0; r < 16; ++r) a[r] = 0.f;

        const int* ip = g_idx + node * 12;
        int base = (node >> 10) << 10;
        #pragma unroll 1
        for (int k = 0; k < 12; ++k) {
            int j = base + ip[k];
            const float4* Qp = (const float4*)&g_Q[(size_t)j * 64 + hq];
            float qv[16];
            #pragma unroll
            for (int p = 0; p < 4; ++p) *(float4*)&qv[p * 4] = Qp[p];
            #pragma unroll
            for (int r = 0; r < 16; ++r)
                a[r] += fmaxf(fmaf(sc[r], R[r] + qv[r], sh[r]), 0.f);
        }
        #pragma unroll
        for (int r = 0; r < 16; ++r) As[hq + r][nloc] = a[r] * (1.f / 12.f);
    }
    __syncthreads();

    int tx = t & 15, ty = t >> 4;
    float acc[4][4];
    #pragma unroll
    for (int m = 0; m < 4; ++m)
        #pragma unroll
        for (int n = 0; n < 4; ++n) acc[m][n] = 0.f;

    #pragma unroll
    for (int h = 0; h < 64; ++h) {
        float a[4], bv[4];
        #pragma unroll
        for (int m = 0; m < 4; ++m) a[m] = As[h][ty * 4 + m];
        #pragma unroll
        for (int n = 0; n < 4; ++n) bv[n] = Ws[h][tx + 16 * n];
        #pragma unroll
        for (int m = 0; m < 4; ++m)
            #pragma unroll
            for (int n = 0; n < 4; ++n) acc[m][n] = fmaf(a[m], bv[n], acc[m][n]);
    }

    #pragma unroll
    for (int n = 0; n < 4; ++n) {
        int o = tx + 16 * n;
        float bo = b2[o];
        #pragma unroll
        for (int m = 0; m < 4; ++m)
            Fout[(size_t)(n0 + ty * 4 + m) * 64 + o] = acc[m][n] + bo;
    }
}

// ---------------- global mean pool over nodes ------------------------------
__global__ void pool_kernel(const float* __restrict__ F) {
    __shared__ float red[4][64];
    int t = threadIdx.x;
    int h = t & 63, s = t >> 6;
    int b = blockIdx.x;
    float acc = 0.f;
    for (int n = s; n < N_; n += 4)
        acc += F[((size_t)b * N_ + n) * H_ + h];
    red[s][h] = acc;
    __syncthreads();
    if (t < 64)
        g_pool[b * H_ + t] = (red[0][t] + red[1][t] + red[2][t] + red[3][t]) * (1.f / N_);
}

// ---------------- FC head ---------------------------------------------------
__global__ void fc_kernel(const float* __restrict__ wf1, const float* __restrict__ bf1,
                          const float* __restrict__ gf,  const float* __restrict__ bef,
                          const float* __restrict__ wf2, const float* __restrict__ bf2,
                          float* __restrict__ out) {
    __shared__ float zs[32][33];
    __shared__ float sc[32], sh[32];
    int t = threadIdx.x;
    int b = t >> 5, j = t & 31;

    float acc = bf1[j];
    #pragma unroll
    for (int h = 0; h < 64; ++h)
        acc = fmaf(g_pool[b * 64 + h], wf1[h * 32 + j], acc);
    zs[b][j] = acc;
    __syncthreads();

    if (t < 32) {
        float s = 0.f;
        for (int q = 0; q < 32; ++q) s += zs[q][t];
        float m = s * (1.f / 32.f);
        float v = 0.f;
        for (int q = 0; q < 32; ++q) { float d = zs[q][t] - m; v = fmaf(d, d, v); }
        v *= (1.f / 32.f);
        float s2 = gf[t] * rsqrtf(v + 1e-5f);
        sc[t] = s2;
        sh[t] = fmaf(-m, s2, bef[t]);
    }
    __syncthreads();

    float r = fmaxf(fmaf(zs[b][j], sc[j], sh[j]), 0.f);
    zs[b][j] = r;
    __syncthreads();

    if (t < 64) {
        int q = t >> 1, o = t & 1;
        float a = bf2[o];
        #pragma unroll
        for (int jj = 0; jj < 32; ++jj)
            a = fmaf(zs[q][jj], wf2[jj * 2 + o], a);
        out[q * 2 + o] = a;
    }
}

// ---------------- host ------------------------------------------------------
template<int CIN>
static void run_layer(const float* Fin, float* Fout,
                      const float* W1, const float* b1,
                      const float* g, const float* be,
                      const float* W2, const float* b2) {
    d2_kernel<CIN><<<4096, 256>>>(Fin);
    dist_kernel<CIN><<<dim3(8, 8, 32), dim3(16, 16)>>>(Fin);
    topk_kernel<<<4096, 256>>>();
    if (CIN == 3) pq3_kernel<<<8192, 256>>>(Fin, W1, b1);
    else          pq64_kernel<<<256, dim3(16, 16)>>>(Fin, W1, b1);
    zero_stats<<<1, 64>>>();
    stats_kernel<<<1024, 256>>>();
    finalize_stats<<<1, 64>>>(g, be);
    bn_mlp2_kernel<<<512, 256>>>(Fout, W2, b2);
}

extern "C" void kernel_launch(void* const* d_in, const int* in_sizes, int n_in,
                              void* d_out, int out_size) {
    const float* x   = (const float*)d_in[0];
    const float* w0a = (const float*)d_in[1];
    const float* b0a = (const float*)d_in[2];
    const float* g0  = (const float*)d_in[3];
    const float* be0 = (const float*)d_in[4];
    const float* w0b = (const float*)d_in[5];
    const float* b0b = (const float*)d_in[6];
    const float* wa  = (const float*)d_in[7];
    const float* ba  = (const float*)d_in[8];
    const float* ga  = (const float*)d_in[9];
    const float* bea = (const float*)d_in[10];
    const float* wb  = (const float*)d_in[11];
    const float* bb  = (const float*)d_in[12];
    const float* wf1 = (const float*)d_in[13];
    const float* bf1 = (const float*)d_in[14];
    const float* gf  = (const float*)d_in[15];
    const float* bef = (const float*)d_in[16];
    const float* wf2 = (const float*)d_in[17];
    const float* bf2 = (const float*)d_in[18];
    float* out = (float*)d_out;

    float *f0 = nullptr, *f1 = nullptr;
    cudaGetSymbolAddress((void**)&f0, g_f0);
    cudaGetSymbolAddress((void**)&f1, g_f1);

    run_layer<3>(x, f0, w0a, b0a, g0, be0, w0b, b0b);
    run_layer<64>(f0, f1, wa,            ba,       ga,       bea,       wb,            bb);
    run_layer<64>(f1, f0, wa + 128 * 64, ba + 64,  ga + 64,  bea + 64,  wb + 64 * 64,  bb + 64);
    run_layer<64>(f0, f1, wa + 256 * 64, ba + 128, ga + 128, bea + 128, wb + 128 * 64, bb + 128);

    pool_kernel<<<32, 256>>>(f1);
    fc_kernel<<<1, 1024>>>(wf1, bf1, gf, bef, wf2, bf2, out);
}